// round 12
// baseline (speedup 1.0000x reference)
#include <cuda_runtime.h>
#include <cuda_fp16.h>
#include <math.h>
#include <stdint.h>

// Problem dims (fixed by the dataset)
#define BB 4
#define LL 2048
#define DD 2048
#define RR 2560
#define MM (BB * LL)      // 8192
#define K4 (4 * RR)       // 10240 (conv fused-K)

// ---------------------------------------------------------------------------
// Device scratch
// ---------------------------------------------------------------------------
__device__ __half g_W1h[(size_t)RR * DD];
__device__ __half g_Wgh[(size_t)2 * RR * RR];  // interleaved: row 2d=wa_d, 2d+1=wx_d
__device__ __half g_W2h[(size_t)DD * RR];
__device__ __half g_Wch[(size_t)RR * K4];
__device__ __half g_Xh [(size_t)MM * DD];
__device__ __half g_H1h[(size_t)MM * RR];     // silu out; later reused for scan h
__device__ __half g_HCh[(size_t)MM * RR];     // conv out
__device__ float  g_Ga [(size_t)MM * RR];
__device__ float  g_Gb [(size_t)MM * RR];
__device__ float  g_CA [(size_t)BB * 32 * RR];
__device__ float  g_CB [(size_t)BB * 32 * RR];
__device__ float  g_sp [RR];

// ---------------------------------------------------------------------------
// helpers / PTX  (base ISA only: mma.sync fp16 + cp.async)
// ---------------------------------------------------------------------------
__device__ __forceinline__ void cpa16(uint32_t dst, const void* src, int sz) {
    asm volatile("cp.async.cg.shared.global [%0], [%1], 16, %2;\n"
                 :: "r"(dst), "l"(src), "r"(sz));
}
__device__ __forceinline__ void mma_f16(float* c, const uint32_t* a, const uint32_t* b) {
    asm volatile(
        "mma.sync.aligned.m16n8k16.row.col.f32.f16.f16.f32 "
        "{%0,%1,%2,%3}, {%4,%5,%6,%7}, {%8,%9}, {%0,%1,%2,%3};\n"
        : "+f"(c[0]), "+f"(c[1]), "+f"(c[2]), "+f"(c[3])
        : "r"(a[0]), "r"(a[1]), "r"(a[2]), "r"(a[3]), "r"(b[0]), "r"(b[1]));
}

// ---------------------------------------------------------------------------
// fp16 tensor-core TN GEMM: C[M,N] = A[M,K] @ W[N,K]^T (+bias)(epilogue)
// CTA tile 64(M) x 128(N) x 64(K halves), 256 threads = 8 warps (2m x 4n),
// warp tile 32x32 (2x4 m16n8k16), 3-stage cp.async pipeline, 2 CTAs/SM.
// Fine-grained tiles minimize wave-quantization tails (96-99% occupancy of
// the last wave vs 86.5% with 128-row tiles).
// CONV: A is a 4-tap time-shifted view of H1 (K=4*RR, lda=RR), zero-padded.
// EPI: 0=none, 1=SiLU, 3=fused RG-LRU gate (writes Ga=C and Gb).
// ---------------------------------------------------------------------------
#define TBM 64
#define TBN 128
#define TKH 64                          // K halves per tile (=128B rows)
#define LDH 72                          // padded lead dim (halves), 144B
#define A_HALVES (TBM * LDH)            // 4608
#define B_HALVES (TBN * LDH)            // 9216
#define STAGE_HALVES (A_HALVES + B_HALVES)
#define STAGE_BYTES  (STAGE_HALVES * 2)          // 27648
#define GSMEM_TOTAL  (3 * STAGE_BYTES)           // 82944 -> 2 CTAs/SM

template<int EPI, bool BIAS, bool CONV, typename TOUT>
__global__ __launch_bounds__(256, 2)
void gemm_mma(const __half* __restrict__ A, const __half* __restrict__ W,
              const float* __restrict__ bias, TOUT* __restrict__ C,
              int N, int K, int lda,
              const __half* __restrict__ hcp, const float* __restrict__ spp,
              const float* __restrict__ bap, const float* __restrict__ bxp,
              float* __restrict__ Gb)
{
    extern __shared__ __half sm[];
    const uint32_t smb = (uint32_t)__cvta_generic_to_shared(sm);

    const int tid  = threadIdx.x;
    const int lane = tid & 31;
    const int wid  = tid >> 5;
    const int g    = lane >> 2;         // 0..7
    const int tq   = lane & 3;          // 0..3
    const int wm   = (wid >> 2) << 5;   // 0 / 32
    const int wn   = (wid & 3) << 5;    // 0,32,64,96
    const int bm   = blockIdx.y * TBM;
    const int bn   = blockIdx.x * TBN;

    float acc[2][4][4];
#pragma unroll
    for (int i = 0; i < 2; i++)
#pragma unroll
        for (int j = 0; j < 4; j++)
#pragma unroll
            for (int c = 0; c < 4; c++) acc[i][j][c] = 0.f;

    const int KT = K / TKH;

    auto issue = [&](int kt, int st) {
        const int k0 = kt * TKH;
        int tap = 0, shift = 0, kcol = k0;
        if (CONV) { tap = k0 / RR; kcol = k0 - tap * RR; shift = 2 * tap - 3; }
        const uint32_t abase = smb + st * STAGE_BYTES;
        const uint32_t bbase = abase + A_HALVES * 2;
        // A: 64 rows x 64 halves (128B) -> 512 x 16B
#pragma unroll
        for (int i = 0; i < 2; i++) {
            int idx = tid + i * 256;
            int row = idx >> 3, seg = idx & 7;
            int m = bm + row, arow = m, sz = 16;
            if (CONV) {
                int t  = m & (LL - 1);
                int ts = t + shift;
                if ((unsigned)ts < (unsigned)LL) arow = m - t + ts;
                else                             sz = 0;     // zero-fill pad row
            }
            cpa16(abase + (uint32_t)(row * (LDH * 2) + seg * 16),
                  A + (size_t)arow * lda + kcol + seg * 8, sz);
        }
        // B: 128 rows x 64 halves -> 1024 x 16B
#pragma unroll
        for (int i = 0; i < 4; i++) {
            int idx = tid + i * 256;
            int row = idx >> 3, seg = idx & 7;
            cpa16(bbase + (uint32_t)(row * (LDH * 2) + seg * 16),
                  W + (size_t)(bn + row) * K + k0 + seg * 8, 16);
        }
        asm volatile("cp.async.commit_group;\n");
    };

    issue(0, 0); issue(1, 1); issue(2, 2);

    for (int kt = 0; kt < KT; kt++) {
        const int st = kt % 3;
        if (kt < KT - 2)       asm volatile("cp.async.wait_group 2;\n");
        else if (kt == KT - 2) asm volatile("cp.async.wait_group 1;\n");
        else                   asm volatile("cp.async.wait_group 0;\n");
        __syncthreads();

        const __half* As = sm + st * STAGE_HALVES;
        const __half* Bs = As + A_HALVES;

#pragma unroll
        for (int s16 = 0; s16 < 4; s16++) {
            const int kk = s16 * 16 + tq * 2;   // half index (even -> 4B aligned)
            uint32_t af[2][4], bf[4][2];
#pragma unroll
            for (int nt = 0; nt < 4; nt++) {
                const __half* bp = Bs + (wn + nt * 8 + g) * LDH + kk;
                bf[nt][0] = *(const uint32_t*)(bp);
                bf[nt][1] = *(const uint32_t*)(bp + 8);
            }
#pragma unroll
            for (int mt = 0; mt < 2; mt++) {
                const __half* ap = As + (wm + mt * 16 + g) * LDH + kk;
                af[mt][0] = *(const uint32_t*)(ap);
                af[mt][1] = *(const uint32_t*)(ap + 8 * LDH);
                af[mt][2] = *(const uint32_t*)(ap + 8);
                af[mt][3] = *(const uint32_t*)(ap + 8 * LDH + 8);
            }
#pragma unroll
            for (int mt = 0; mt < 2; mt++)
#pragma unroll
                for (int nt = 0; nt < 4; nt++)
                    mma_f16(acc[mt][nt], af[mt], bf[nt]);
        }
        __syncthreads();

        const int kn = kt + 3;
        if (kn < KT) issue(kn, st);
    }

    // Epilogue: c0,c1 -> (row g, col tq*2..+1); c2,c3 -> row g+8
#pragma unroll
    for (int mt = 0; mt < 2; mt++) {
        const int r0 = bm + wm + mt * 16 + g;
#pragma unroll
        for (int nt = 0; nt < 4; nt++) {
            const int col = bn + wn + nt * 8 + tq * 2;
            if (EPI == 3) {
                // fused RG-LRU gate: col pair (2d, 2d+1) = (rl, il) for channel d
                const int d = col >> 1;
                const float ba_ = __ldg(bap + d);
                const float bx_ = __ldg(bxp + d);
                const float sp_ = __ldg(spp + d);
                const float hc0 = __half2float(hcp[(size_t)r0 * RR + d]);
                const float hc8 = __half2float(hcp[(size_t)(r0 + 8) * RR + d]);
                float rl0 = acc[mt][nt][0] + ba_, il0 = acc[mt][nt][1] + bx_;
                float rl8 = acc[mt][nt][2] + ba_, il8 = acc[mt][nt][3] + bx_;
                float a0 = __expf(sp_ / (1.f + __expf(-rl0)));
                float a8 = __expf(sp_ / (1.f + __expf(-rl8)));
                float b0 = sqrtf(fmaxf(1.f - a0 * a0, 0.f)) * hc0 / (1.f + __expf(-il0));
                float b8 = sqrtf(fmaxf(1.f - a8 * a8, 0.f)) * hc8 / (1.f + __expf(-il8));
                ((float*)C)[(size_t)r0 * RR + d]       = a0;
                ((float*)C)[(size_t)(r0 + 8) * RR + d] = a8;
                Gb[(size_t)r0 * RR + d]       = b0;
                Gb[(size_t)(r0 + 8) * RR + d] = b8;
            } else {
                float bx_ = 0.f, by_ = 0.f;
                if (BIAS) { float2 bb = *(const float2*)(bias + col); bx_ = bb.x; by_ = bb.y; }
                float v[4] = { acc[mt][nt][0] + bx_, acc[mt][nt][1] + by_,
                               acc[mt][nt][2] + bx_, acc[mt][nt][3] + by_ };
                if (EPI == 1) {
#pragma unroll
                    for (int j = 0; j < 4; j++) v[j] = v[j] / (1.f + __expf(-v[j]));
                }
                if (sizeof(TOUT) == 2) {
                    __half2* c0 = (__half2*)((__half*)C + (size_t)r0 * N + col);
                    __half2* c1 = (__half2*)((__half*)C + (size_t)(r0 + 8) * N + col);
                    *c0 = __floats2half2_rn(v[0], v[1]);
                    *c1 = __floats2half2_rn(v[2], v[3]);
                } else {
                    *(float2*)((float*)C + (size_t)r0 * N + col)       = make_float2(v[0], v[1]);
                    *(float2*)((float*)C + (size_t)(r0 + 8) * N + col) = make_float2(v[2], v[3]);
                }
            }
        }
    }
}

// ---------------------------------------------------------------------------
// prep kernels (vectorized: float4 reads, packed half writes)
// ---------------------------------------------------------------------------
__device__ __forceinline__ uint32_t h2bits(float a, float b) {
    __half2 h = __floats2half2_rn(a, b);
    return *(const uint32_t*)&h;
}

// 8 floats -> 8 halves per thread (16B in x2, 16B out)
__global__ void half_copy8(const float4* __restrict__ in, uint4* __restrict__ out)
{
    size_t i = (size_t)blockIdx.x * 256 + threadIdx.x;
    float4 a = in[2 * i], b = in[2 * i + 1];
    uint4 o;
    o.x = h2bits(a.x, a.y); o.y = h2bits(a.z, a.w);
    o.z = h2bits(b.x, b.y); o.w = h2bits(b.z, b.w);
    out[i] = o;
}

// interleave wa/wx rows, 4 cols per thread: out row 2d=wa_d, 2d+1=wx_d
__global__ void pack_gates4(const float* __restrict__ wa, const float* __restrict__ wx,
                            uint2* __restrict__ out)
{
    int idx = blockIdx.x * 256 + threadIdx.x;      // j*(RR/4)+q, 2*RR*RR/4 total
    int j = idx / (RR / 4);
    int q = idx - j * (RR / 4);
    const float4* src = (const float4*)((j & 1) ? wx : wa) + (size_t)(j >> 1) * (RR / 4) + q;
    float4 v = *src;
    uint2 o;
    o.x = h2bits(v.x, v.y); o.y = h2bits(v.z, v.w);
    out[idx] = o;
}

// conv_w [o][i][t] -> Wch [o][t*R + i]; float4 read = all 4 taps of (o,i)
__global__ void conv_pack4(const float4* __restrict__ cw4, __half* __restrict__ wch)
{
    int T = blockIdx.x * 256 + threadIdx.x;        // o*RR + i, RR*RR total
    int o = T / RR;
    int i = T - o * RR;
    float4 v = cw4[T];
    size_t base = (size_t)o * K4 + i;
    wch[base]          = __float2half_rn(v.x);
    wch[base + RR]     = __float2half_rn(v.y);
    wch[base + 2 * RR] = __float2half_rn(v.z);
    wch[base + 3 * RR] = __float2half_rn(v.w);
}

__global__ void prep_sp(const float* __restrict__ lam, float* __restrict__ sp)
{
    int d = blockIdx.x * 256 + threadIdx.x;
    if (d < RR) {
        float l = lam[d];
        float s = (l > 20.f) ? l : log1pf(expf(l));
        sp[d] = -8.f * s;
    }
}

// ---- 3-phase chunked scan: L=2048 -> 32 chunks x 64 steps ----
#define SCH 32
#define SCL 64

__global__ void scan_p1(const float* __restrict__ a, const float* __restrict__ bv,
                        float* __restrict__ CA, float* __restrict__ CB)
{
    int gid = blockIdx.x * 256 + threadIdx.x;          // BB*SCH*RR total
    int b   = gid / (SCH * RR);
    int rem = gid - b * (SCH * RR);
    int c   = rem / RR;
    int d   = rem - c * RR;
    size_t base = ((size_t)b * LL + (size_t)c * SCL) * RR + d;
    float Ap = 1.f, h = 0.f;
#pragma unroll 4
    for (int t = 0; t < SCL; t++) {
        size_t off = base + (size_t)t * RR;
        float at = a[off];
        Ap *= at;
        h = fmaf(at, h, bv[off]);
    }
    CA[gid] = Ap;
    CB[gid] = h;
}

__global__ void scan_p2(float* __restrict__ CA, float* __restrict__ CB)
{
    int gid = blockIdx.x * 256 + threadIdx.x;          // BB*RR total
    int b = gid / RR;
    int d = gid - b * RR;
    float h = 0.f;
#pragma unroll
    for (int c = 0; c < SCH; c++) {
        size_t idx = ((size_t)b * SCH + c) * RR + d;
        float A = CA[idx], Bv = CB[idx];
        CB[idx] = h;                 // carry-in for chunk c
        h = fmaf(A, h, Bv);
    }
}

__global__ void scan_p3(const float* __restrict__ a, const float* __restrict__ bv,
                        const float* __restrict__ CB, __half* __restrict__ h)
{
    int gid = blockIdx.x * 256 + threadIdx.x;
    int b   = gid / (SCH * RR);
    int rem = gid - b * (SCH * RR);
    int c   = rem / RR;
    int d   = rem - c * RR;
    size_t base = ((size_t)b * LL + (size_t)c * SCL) * RR + d;
    float hp = CB[gid];
#pragma unroll 4
    for (int t = 0; t < SCL; t++) {
        size_t off = base + (size_t)t * RR;
        hp = fmaf(a[off], hp, bv[off]);
        h[off] = __float2half_rn(hp);
    }
}

// ---------------------------------------------------------------------------
extern "C" void kernel_launch(void* const* d_in, const int* in_sizes, int n_in,
                              void* d_out, int out_size)
{
    const float* x      = (const float*)d_in[0];
    const float* w1     = (const float*)d_in[1];
    const float* b1     = (const float*)d_in[2];
    const float* conv_w = (const float*)d_in[3];
    const float* conv_b = (const float*)d_in[4];
    const float* wa     = (const float*)d_in[5];
    const float* ba     = (const float*)d_in[6];
    const float* wx     = (const float*)d_in[7];
    const float* bx     = (const float*)d_in[8];
    const float* lam    = (const float*)d_in[9];
    const float* w2     = (const float*)d_in[10];
    const float* b2     = (const float*)d_in[11];
    float* out = (float*)d_out;

    __half *W1h, *Wgh, *W2h, *Wch, *Xh, *H1h, *HCh;
    float  *Ga, *Gb, *CA, *CB, *sp;
    cudaGetSymbolAddress((void**)&W1h, g_W1h);
    cudaGetSymbolAddress((void**)&Wgh, g_Wgh);
    cudaGetSymbolAddress((void**)&W2h, g_W2h);
    cudaGetSymbolAddress((void**)&Wch, g_Wch);
    cudaGetSymbolAddress((void**)&Xh,  g_Xh);
    cudaGetSymbolAddress((void**)&H1h, g_H1h);
    cudaGetSymbolAddress((void**)&HCh, g_HCh);
    cudaGetSymbolAddress((void**)&Ga,  g_Ga);
    cudaGetSymbolAddress((void**)&Gb,  g_Gb);
    cudaGetSymbolAddress((void**)&CA,  g_CA);
    cudaGetSymbolAddress((void**)&CB,  g_CB);
    cudaGetSymbolAddress((void**)&sp,  g_sp);

    cudaFuncSetAttribute(gemm_mma<1, true,  false, __half>, cudaFuncAttributeMaxDynamicSharedMemorySize, GSMEM_TOTAL);
    cudaFuncSetAttribute(gemm_mma<0, true,  true,  __half>, cudaFuncAttributeMaxDynamicSharedMemorySize, GSMEM_TOTAL);
    cudaFuncSetAttribute(gemm_mma<3, false, false, float >, cudaFuncAttributeMaxDynamicSharedMemorySize, GSMEM_TOTAL);
    cudaFuncSetAttribute(gemm_mma<0, true,  false, float >, cudaFuncAttributeMaxDynamicSharedMemorySize, GSMEM_TOTAL);

    // side stream + fork/join events (created once; host-side objects only)
    static cudaStream_t s2 = nullptr;
    static cudaEvent_t evFork = nullptr, evJoin = nullptr;
    if (!s2) {
        cudaStreamCreateWithFlags(&s2, cudaStreamNonBlocking);
        cudaEventCreateWithFlags(&evFork, cudaEventDisableTiming);
        cudaEventCreateWithFlags(&evJoin, cudaEventDisableTiming);
    }

    // fork: weight prep for later GEMMs runs concurrently with x-prep + gemm1
    cudaEventRecord(evFork, 0);
    cudaStreamWaitEvent(s2, evFork, 0);
    conv_pack4<<<(RR * RR) / 256, 256, 0, s2>>>((const float4*)conv_w, Wch);
    pack_gates4<<<(2 * RR * RR / 4) / 256, 256, 0, s2>>>(wa, wx, (uint2*)Wgh);
    half_copy8<<<((size_t)DD * RR / 8) / 256, 256, 0, s2>>>((const float4*)w2, (uint4*)W2h);
    prep_sp<<<(RR + 255) / 256, 256, 0, s2>>>(lam, sp);
    cudaEventRecord(evJoin, s2);

    // main stream: inputs for gemm1
    half_copy8<<<((size_t)MM * DD / 8) / 256, 256>>>((const float4*)x,  (uint4*)Xh);
    half_copy8<<<((size_t)RR * DD / 8) / 256, 256>>>((const float4*)w1, (uint4*)W1h);

    dim3 blk(256);
    dim3 gN2560(RR / TBN,     MM / TBM);   // 20 x 128 = 2560
    dim3 gN5120(2 * RR / TBN, MM / TBM);   // 40 x 128 = 5120
    dim3 gN2048(DD / TBN,     MM / TBM);   // 16 x 128 = 2048

    // 1) H1 = h( silu(x @ w1^T + b1) )
    gemm_mma<1, true,  false, __half><<<gN2560, blk, GSMEM_TOTAL>>>(
        Xh, W1h, b1, H1h, RR, DD, DD, nullptr, nullptr, nullptr, nullptr, nullptr);

    // join: Wch/Wgh/W2h/sp ready before they are consumed
    cudaStreamWaitEvent(0, evJoin, 0);

    // 2) HC = h( conv(H1) + conv_b )  — single fused GEMM, K = 4*R
    gemm_mma<0, true,  true,  __half><<<gN2560, blk, GSMEM_TOTAL>>>(
        H1h, Wch, conv_b, HCh, RR, K4, RR, nullptr, nullptr, nullptr, nullptr, nullptr);
    // 3+4) Ga/Gb = fused( HC @ [wa|wx interleaved]^T , gate math )
    gemm_mma<3, false, false, float ><<<gN5120, blk, GSMEM_TOTAL>>>(
        HCh, Wgh, nullptr, Ga, 2 * RR, RR, RR, HCh, sp, ba, bx, Gb);
    // 5) chunked parallel scan -> h (half, into H1h)
    scan_p1<<<(BB * SCH * RR) / 256, 256>>>(Ga, Gb, CA, CB);
    scan_p2<<<(BB * RR) / 256, 256>>>(CA, CB);
    scan_p3<<<(BB * SCH * RR) / 256, 256>>>(Ga, Gb, CB, H1h);
    // 6) out = h @ w2^T + b2  (f32)
    gemm_mma<0, true,  false, float ><<<gN2048, blk, GSMEM_TOTAL>>>(
        H1h, W2h, b2, out, DD, RR, RR, nullptr, nullptr, nullptr, nullptr, nullptr);
}

// round 15
// speedup vs baseline: 1.2948x; 1.2948x over previous
#include <cuda_runtime.h>
#include <cuda_fp16.h>
#include <math.h>
#include <stdint.h>

// Problem dims (fixed by the dataset)
#define BB 4
#define LL 2048
#define DD 2048
#define RR 2560
#define MM (BB * LL)      // 8192
#define K4 (4 * RR)       // 10240 (conv fused-K)
#define MH (MM / 2)       // 4096 rows per half (2 batches)

// ---------------------------------------------------------------------------
// Device scratch
// ---------------------------------------------------------------------------
__device__ __half g_W1h[(size_t)RR * DD];
__device__ __half g_Wgh[(size_t)2 * RR * RR];  // interleaved: row 2d=wa_d, 2d+1=wx_d
__device__ __half g_W2h[(size_t)DD * RR];
__device__ __half g_Wch[(size_t)RR * K4];
__device__ __half g_Xh [(size_t)MM * DD];
__device__ __half g_H1h[(size_t)MM * RR];     // silu out; later reused for scan h
__device__ __half g_HCh[(size_t)MM * RR];     // conv out
__device__ float  g_Ga [(size_t)MM * RR];
__device__ float  g_Gb [(size_t)MM * RR];
__device__ float  g_CA [(size_t)BB * 32 * RR];
__device__ float  g_CB [(size_t)BB * 32 * RR];
__device__ float  g_sp [RR];

// ---------------------------------------------------------------------------
// helpers / PTX  (base ISA only: mma.sync fp16 + cp.async)
// ---------------------------------------------------------------------------
__device__ __forceinline__ void cpa16(uint32_t dst, const void* src, int sz) {
    asm volatile("cp.async.cg.shared.global [%0], [%1], 16, %2;\n"
                 :: "r"(dst), "l"(src), "r"(sz));
}
__device__ __forceinline__ void mma_f16(float* c, const uint32_t* a, const uint32_t* b) {
    asm volatile(
        "mma.sync.aligned.m16n8k16.row.col.f32.f16.f16.f32 "
        "{%0,%1,%2,%3}, {%4,%5,%6,%7}, {%8,%9}, {%0,%1,%2,%3};\n"
        : "+f"(c[0]), "+f"(c[1]), "+f"(c[2]), "+f"(c[3])
        : "r"(a[0]), "r"(a[1]), "r"(a[2]), "r"(a[3]), "r"(b[0]), "r"(b[1]));
}

// ---------------------------------------------------------------------------
// fp16 tensor-core TN GEMM: C[M,N] = A[M,K] @ W[N,K]^T (+bias)(epilogue)
// CTA tile 128(M) x 128(N) x 64(K halves), 256 threads = 8 warps (2m x 4n),
// warp tile 64x32 (4x4 m16n8k16), 3-stage cp.async pipeline, 2 CTAs/SM.
// (R9 geometry — fastest measured; M64 variant regressed, see R11.)
// CONV: A is a 4-tap time-shifted view of H1 (K=4*RR, lda=RR), zero-padded.
//       Caller may offset A/C by whole batches (multiples of LL rows).
// EPI: 0=none, 1=SiLU, 3=fused RG-LRU gate (writes Ga=C and Gb).
// ---------------------------------------------------------------------------
#define TBN 128
#define TKH 64                          // K halves per tile (=128B rows)
#define LDH 72                          // padded lead dim (halves), 144B
#define A_HALVES (128 * LDH)            // 9216
#define B_HALVES (TBN * LDH)            // 9216
#define STAGE_HALVES (A_HALVES + B_HALVES)
#define STAGE_BYTES  (STAGE_HALVES * 2)          // 36864
#define GSMEM_TOTAL  (3 * STAGE_BYTES)           // 110592 -> 2 CTAs/SM

template<int EPI, bool BIAS, bool CONV, typename TOUT>
__global__ __launch_bounds__(256, 2)
void gemm_mma(const __half* __restrict__ A, const __half* __restrict__ W,
              const float* __restrict__ bias, TOUT* __restrict__ C,
              int N, int K, int lda,
              const __half* __restrict__ hcp, const float* __restrict__ spp,
              const float* __restrict__ bap, const float* __restrict__ bxp,
              float* __restrict__ Gb)
{
    extern __shared__ __half sm[];
    const uint32_t smb = (uint32_t)__cvta_generic_to_shared(sm);

    const int tid  = threadIdx.x;
    const int lane = tid & 31;
    const int wid  = tid >> 5;
    const int g    = lane >> 2;         // 0..7
    const int tq   = lane & 3;          // 0..3
    const int wm   = (wid >> 2) << 6;   // 0 / 64
    const int wn   = (wid & 3) << 5;    // 0,32,64,96
    const int bm   = blockIdx.y * 128;
    const int bn   = blockIdx.x * TBN;

    float acc[4][4][4];
#pragma unroll
    for (int i = 0; i < 4; i++)
#pragma unroll
        for (int j = 0; j < 4; j++)
#pragma unroll
            for (int c = 0; c < 4; c++) acc[i][j][c] = 0.f;

    const int KT = K / TKH;

    auto issue = [&](int kt, int st) {
        const int k0 = kt * TKH;
        int tap = 0, shift = 0, kcol = k0;
        if (CONV) { tap = k0 / RR; kcol = k0 - tap * RR; shift = 2 * tap - 3; }
        const uint32_t abase = smb + st * STAGE_BYTES;
        const uint32_t bbase = abase + A_HALVES * 2;
        // A: 128 rows x 64 halves (128B) -> 1024 x 16B
#pragma unroll
        for (int i = 0; i < 4; i++) {
            int idx = tid + i * 256;
            int row = idx >> 3, seg = idx & 7;
            int m = bm + row, arow = m, sz = 16;
            if (CONV) {
                int t  = m & (LL - 1);
                int ts = t + shift;
                if ((unsigned)ts < (unsigned)LL) arow = m - t + ts;
                else                             sz = 0;     // zero-fill pad row
            }
            cpa16(abase + (uint32_t)(row * (LDH * 2) + seg * 16),
                  A + (size_t)arow * lda + kcol + seg * 8, sz);
        }
        // B: 128 rows x 64 halves -> 1024 x 16B
#pragma unroll
        for (int i = 0; i < 4; i++) {
            int idx = tid + i * 256;
            int row = idx >> 3, seg = idx & 7;
            cpa16(bbase + (uint32_t)(row * (LDH * 2) + seg * 16),
                  W + (size_t)(bn + row) * K + k0 + seg * 8, 16);
        }
        asm volatile("cp.async.commit_group;\n");
    };

    issue(0, 0); issue(1, 1); issue(2, 2);

    for (int kt = 0; kt < KT; kt++) {
        const int st = kt % 3;
        if (kt < KT - 2)       asm volatile("cp.async.wait_group 2;\n");
        else if (kt == KT - 2) asm volatile("cp.async.wait_group 1;\n");
        else                   asm volatile("cp.async.wait_group 0;\n");
        __syncthreads();

        const __half* As = sm + st * STAGE_HALVES;
        const __half* Bs = As + A_HALVES;

#pragma unroll
        for (int s16 = 0; s16 < 4; s16++) {
            const int kk = s16 * 16 + tq * 2;   // half index (even -> 4B aligned)
            uint32_t af[4][4], bf[4][2];
#pragma unroll
            for (int nt = 0; nt < 4; nt++) {
                const __half* bp = Bs + (wn + nt * 8 + g) * LDH + kk;
                bf[nt][0] = *(const uint32_t*)(bp);
                bf[nt][1] = *(const uint32_t*)(bp + 8);
            }
#pragma unroll
            for (int mt = 0; mt < 4; mt++) {
                const __half* ap = As + (wm + mt * 16 + g) * LDH + kk;
                af[mt][0] = *(const uint32_t*)(ap);
                af[mt][1] = *(const uint32_t*)(ap + 8 * LDH);
                af[mt][2] = *(const uint32_t*)(ap + 8);
                af[mt][3] = *(const uint32_t*)(ap + 8 * LDH + 8);
            }
#pragma unroll
            for (int mt = 0; mt < 4; mt++)
#pragma unroll
                for (int nt = 0; nt < 4; nt++)
                    mma_f16(acc[mt][nt], af[mt], bf[nt]);
        }
        __syncthreads();

        const int kn = kt + 3;
        if (kn < KT) issue(kn, st);
    }

    // Epilogue: c0,c1 -> (row g, col tq*2..+1); c2,c3 -> row g+8
#pragma unroll
    for (int mt = 0; mt < 4; mt++) {
        const int r0 = bm + wm + mt * 16 + g;
#pragma unroll
        for (int nt = 0; nt < 4; nt++) {
            const int col = bn + wn + nt * 8 + tq * 2;
            if (EPI == 3) {
                // fused RG-LRU gate: col pair (2d, 2d+1) = (rl, il) for channel d
                const int d = col >> 1;
                const float ba_ = __ldg(bap + d);
                const float bx_ = __ldg(bxp + d);
                const float sp_ = __ldg(spp + d);
                const float hc0 = __half2float(hcp[(size_t)r0 * RR + d]);
                const float hc8 = __half2float(hcp[(size_t)(r0 + 8) * RR + d]);
                float rl0 = acc[mt][nt][0] + ba_, il0 = acc[mt][nt][1] + bx_;
                float rl8 = acc[mt][nt][2] + ba_, il8 = acc[mt][nt][3] + bx_;
                float a0 = __expf(sp_ / (1.f + __expf(-rl0)));
                float a8 = __expf(sp_ / (1.f + __expf(-rl8)));
                float b0 = sqrtf(fmaxf(1.f - a0 * a0, 0.f)) * hc0 / (1.f + __expf(-il0));
                float b8 = sqrtf(fmaxf(1.f - a8 * a8, 0.f)) * hc8 / (1.f + __expf(-il8));
                ((float*)C)[(size_t)r0 * RR + d]       = a0;
                ((float*)C)[(size_t)(r0 + 8) * RR + d] = a8;
                Gb[(size_t)r0 * RR + d]       = b0;
                Gb[(size_t)(r0 + 8) * RR + d] = b8;
            } else {
                float bx_ = 0.f, by_ = 0.f;
                if (BIAS) { float2 bb = *(const float2*)(bias + col); bx_ = bb.x; by_ = bb.y; }
                float v[4] = { acc[mt][nt][0] + bx_, acc[mt][nt][1] + by_,
                               acc[mt][nt][2] + bx_, acc[mt][nt][3] + by_ };
                if (EPI == 1) {
#pragma unroll
                    for (int j = 0; j < 4; j++) v[j] = v[j] / (1.f + __expf(-v[j]));
                }
                if (sizeof(TOUT) == 2) {
                    __half2* c0 = (__half2*)((__half*)C + (size_t)r0 * N + col);
                    __half2* c1 = (__half2*)((__half*)C + (size_t)(r0 + 8) * N + col);
                    *c0 = __floats2half2_rn(v[0], v[1]);
                    *c1 = __floats2half2_rn(v[2], v[3]);
                } else {
                    *(float2*)((float*)C + (size_t)r0 * N + col)       = make_float2(v[0], v[1]);
                    *(float2*)((float*)C + (size_t)(r0 + 8) * N + col) = make_float2(v[2], v[3]);
                }
            }
        }
    }
}

// ---------------------------------------------------------------------------
// prep kernels (vectorized: float4 reads, packed half writes)
// ---------------------------------------------------------------------------
__device__ __forceinline__ uint32_t h2bits(float a, float b) {
    __half2 h = __floats2half2_rn(a, b);
    return *(const uint32_t*)&h;
}

// 8 floats -> 8 halves per thread (16B in x2, 16B out)
__global__ void half_copy8(const float4* __restrict__ in, uint4* __restrict__ out)
{
    size_t i = (size_t)blockIdx.x * 256 + threadIdx.x;
    float4 a = in[2 * i], b = in[2 * i + 1];
    uint4 o;
    o.x = h2bits(a.x, a.y); o.y = h2bits(a.z, a.w);
    o.z = h2bits(b.x, b.y); o.w = h2bits(b.z, b.w);
    out[i] = o;
}

// interleave wa/wx rows, 4 cols per thread: out row 2d=wa_d, 2d+1=wx_d
__global__ void pack_gates4(const float* __restrict__ wa, const float* __restrict__ wx,
                            uint2* __restrict__ out)
{
    int idx = blockIdx.x * 256 + threadIdx.x;      // j*(RR/4)+q, 2*RR*RR/4 total
    int j = idx / (RR / 4);
    int q = idx - j * (RR / 4);
    const float4* src = (const float4*)((j & 1) ? wx : wa) + (size_t)(j >> 1) * (RR / 4) + q;
    float4 v = *src;
    uint2 o;
    o.x = h2bits(v.x, v.y); o.y = h2bits(v.z, v.w);
    out[idx] = o;
}

// conv_w [o][i][t] -> Wch [o][t*R + i]; float4 read = all 4 taps of (o,i)
__global__ void conv_pack4(const float4* __restrict__ cw4, __half* __restrict__ wch)
{
    int T = blockIdx.x * 256 + threadIdx.x;        // o*RR + i, RR*RR total
    int o = T / RR;
    int i = T - o * RR;
    float4 v = cw4[T];
    size_t base = (size_t)o * K4 + i;
    wch[base]          = __float2half_rn(v.x);
    wch[base + RR]     = __float2half_rn(v.y);
    wch[base + 2 * RR] = __float2half_rn(v.z);
    wch[base + 3 * RR] = __float2half_rn(v.w);
}

__global__ void prep_sp(const float* __restrict__ lam, float* __restrict__ sp)
{
    int d = blockIdx.x * 256 + threadIdx.x;
    if (d < RR) {
        float l = lam[d];
        float s = (l > 20.f) ? l : log1pf(expf(l));
        sp[d] = -8.f * s;
    }
}

// ---- 3-phase chunked scan: L=2048 -> 32 chunks x 64 steps ----
// Batch-relative: caller offsets a/bv/CA/CB/h pointers by whole batches.
#define SCH 32
#define SCL 64

__global__ void scan_p1(const float* __restrict__ a, const float* __restrict__ bv,
                        float* __restrict__ CA, float* __restrict__ CB)
{
    int gid = blockIdx.x * 256 + threadIdx.x;          // nb*SCH*RR total
    int b   = gid / (SCH * RR);
    int rem = gid - b * (SCH * RR);
    int c   = rem / RR;
    int d   = rem - c * RR;
    size_t base = ((size_t)b * LL + (size_t)c * SCL) * RR + d;
    float Ap = 1.f, h = 0.f;
#pragma unroll 4
    for (int t = 0; t < SCL; t++) {
        size_t off = base + (size_t)t * RR;
        float at = a[off];
        Ap *= at;
        h = fmaf(at, h, bv[off]);
    }
    CA[gid] = Ap;
    CB[gid] = h;
}

__global__ void scan_p2(float* __restrict__ CA, float* __restrict__ CB)
{
    int gid = blockIdx.x * 256 + threadIdx.x;          // nb*RR total
    int b = gid / RR;
    int d = gid - b * RR;
    float h = 0.f;
#pragma unroll
    for (int c = 0; c < SCH; c++) {
        size_t idx = ((size_t)b * SCH + c) * RR + d;
        float A = CA[idx], Bv = CB[idx];
        CB[idx] = h;                 // carry-in for chunk c
        h = fmaf(A, h, Bv);
    }
}

__global__ void scan_p3(const float* __restrict__ a, const float* __restrict__ bv,
                        const float* __restrict__ CB, __half* __restrict__ h)
{
    int gid = blockIdx.x * 256 + threadIdx.x;
    int b   = gid / (SCH * RR);
    int rem = gid - b * (SCH * RR);
    int c   = rem / RR;
    int d   = rem - c * RR;
    size_t base = ((size_t)b * LL + (size_t)c * SCL) * RR + d;
    float hp = CB[gid];
#pragma unroll 4
    for (int t = 0; t < SCL; t++) {
        size_t off = base + (size_t)t * RR;
        hp = fmaf(a[off], hp, bv[off]);
        h[off] = __float2half_rn(hp);
    }
}

// ---------------------------------------------------------------------------
extern "C" void kernel_launch(void* const* d_in, const int* in_sizes, int n_in,
                              void* d_out, int out_size)
{
    const float* x      = (const float*)d_in[0];
    const float* w1     = (const float*)d_in[1];
    const float* b1     = (const float*)d_in[2];
    const float* conv_w = (const float*)d_in[3];
    const float* conv_b = (const float*)d_in[4];
    const float* wa     = (const float*)d_in[5];
    const float* ba     = (const float*)d_in[6];
    const float* wx     = (const float*)d_in[7];
    const float* bx     = (const float*)d_in[8];
    const float* lam    = (const float*)d_in[9];
    const float* w2     = (const float*)d_in[10];
    const float* b2     = (const float*)d_in[11];
    float* out = (float*)d_out;

    __half *W1h, *Wgh, *W2h, *Wch, *Xh, *H1h, *HCh;
    float  *Ga, *Gb, *CA, *CB, *sp;
    cudaGetSymbolAddress((void**)&W1h, g_W1h);
    cudaGetSymbolAddress((void**)&Wgh, g_Wgh);
    cudaGetSymbolAddress((void**)&W2h, g_W2h);
    cudaGetSymbolAddress((void**)&Wch, g_Wch);
    cudaGetSymbolAddress((void**)&Xh,  g_Xh);
    cudaGetSymbolAddress((void**)&H1h, g_H1h);
    cudaGetSymbolAddress((void**)&HCh, g_HCh);
    cudaGetSymbolAddress((void**)&Ga,  g_Ga);
    cudaGetSymbolAddress((void**)&Gb,  g_Gb);
    cudaGetSymbolAddress((void**)&CA,  g_CA);
    cudaGetSymbolAddress((void**)&CB,  g_CB);
    cudaGetSymbolAddress((void**)&sp,  g_sp);

    cudaFuncSetAttribute(gemm_mma<1, true,  false, __half>, cudaFuncAttributeMaxDynamicSharedMemorySize, GSMEM_TOTAL);
    cudaFuncSetAttribute(gemm_mma<0, true,  true,  __half>, cudaFuncAttributeMaxDynamicSharedMemorySize, GSMEM_TOTAL);
    cudaFuncSetAttribute(gemm_mma<3, false, false, float >, cudaFuncAttributeMaxDynamicSharedMemorySize, GSMEM_TOTAL);
    cudaFuncSetAttribute(gemm_mma<0, true,  false, float >, cudaFuncAttributeMaxDynamicSharedMemorySize, GSMEM_TOTAL);

    // streams + events (created once; host-side objects only)
    static cudaStream_t s2 = nullptr, sB = nullptr;
    static cudaEvent_t evFork = nullptr, evW1 = nullptr, evWch = nullptr,
                       evWg = nullptr, evW2 = nullptr, evB = nullptr;
    if (!s2) {
        cudaStreamCreateWithFlags(&s2, cudaStreamNonBlocking);
        cudaStreamCreateWithFlags(&sB, cudaStreamNonBlocking);
        cudaEventCreateWithFlags(&evFork, cudaEventDisableTiming);
        cudaEventCreateWithFlags(&evW1,   cudaEventDisableTiming);
        cudaEventCreateWithFlags(&evWch,  cudaEventDisableTiming);
        cudaEventCreateWithFlags(&evWg,   cudaEventDisableTiming);
        cudaEventCreateWithFlags(&evW2,   cudaEventDisableTiming);
        cudaEventCreateWithFlags(&evB,    cudaEventDisableTiming);
    }

    dim3 blk(256);
    dim3 g1h(RR / TBN,     MH / 128);   // 20 x 32 (gemm1/conv per half)
    dim3 ggh(2 * RR / TBN, MH / 128);   // 40 x 32 (gate per half)
    dim3 g2h(DD / TBN,     MH / 128);   // 16 x 32 (gemm2 per half)

    const size_t offR = (size_t)MH * RR;       // half offset in R-width buffers
    const size_t offD = (size_t)MH * DD;       // half offset in D-width buffers
    const size_t offC = (size_t)2 * SCH * RR;  // half offset in carry buffers

    // ---- weight-prep stream (ordered so earliest consumers unblock first) ----
    cudaEventRecord(evFork, 0);
    cudaStreamWaitEvent(s2, evFork, 0);
    half_copy8<<<((size_t)RR * DD / 8) / 256, 256, 0, s2>>>((const float4*)w1, (uint4*)W1h);
    cudaEventRecord(evW1, s2);
    conv_pack4<<<(RR * RR) / 256, 256, 0, s2>>>((const float4*)conv_w, Wch);
    cudaEventRecord(evWch, s2);
    pack_gates4<<<(2 * RR * RR / 4) / 256, 256, 0, s2>>>(wa, wx, (uint2*)Wgh);
    prep_sp<<<(RR + 255) / 256, 256, 0, s2>>>(lam, sp);
    cudaEventRecord(evWg, s2);
    half_copy8<<<((size_t)DD * RR / 8) / 256, 256, 0, s2>>>((const float4*)w2, (uint4*)W2h);
    cudaEventRecord(evW2, s2);

    // ---- chain B (half 1: batches 2-3) ----
    cudaStreamWaitEvent(sB, evFork, 0);
    half_copy8<<<(offD / 8) / 256, 256, 0, sB>>>((const float4*)(x + offD), (uint4*)(Xh + offD));
    cudaStreamWaitEvent(sB, evW1, 0);
    gemm_mma<1, true,  false, __half><<<g1h, blk, GSMEM_TOTAL, sB>>>(
        Xh + offD, W1h, b1, H1h + offR, RR, DD, DD, nullptr, nullptr, nullptr, nullptr, nullptr);
    cudaStreamWaitEvent(sB, evWch, 0);
    gemm_mma<0, true,  true,  __half><<<g1h, blk, GSMEM_TOTAL, sB>>>(
        H1h + offR, Wch, conv_b, HCh + offR, RR, K4, RR, nullptr, nullptr, nullptr, nullptr, nullptr);
    cudaStreamWaitEvent(sB, evWg, 0);
    gemm_mma<3, false, false, float ><<<ggh, blk, GSMEM_TOTAL, sB>>>(
        HCh + offR, Wgh, nullptr, Ga + offR, 2 * RR, RR, RR, HCh + offR, sp, ba, bx, Gb + offR);
    scan_p1<<<(2 * SCH * RR) / 256, 256, 0, sB>>>(Ga + offR, Gb + offR, CA + offC, CB + offC);
    scan_p2<<<(2 * RR) / 256, 256, 0, sB>>>(CA + offC, CB + offC);
    scan_p3<<<(2 * SCH * RR) / 256, 256, 0, sB>>>(Ga + offR, Gb + offR, CB + offC, H1h + offR);
    cudaStreamWaitEvent(sB, evW2, 0);
    gemm_mma<0, true,  false, float ><<<g2h, blk, GSMEM_TOTAL, sB>>>(
        H1h + offR, W2h, b2, out + offD, DD, RR, RR, nullptr, nullptr, nullptr, nullptr, nullptr);
    cudaEventRecord(evB, sB);

    // ---- chain A (half 0: batches 0-1) on the main stream ----
    half_copy8<<<(offD / 8) / 256, 256>>>((const float4*)x, (uint4*)Xh);
    cudaStreamWaitEvent(0, evW1, 0);
    gemm_mma<1, true,  false, __half><<<g1h, blk, GSMEM_TOTAL>>>(
        Xh, W1h, b1, H1h, RR, DD, DD, nullptr, nullptr, nullptr, nullptr, nullptr);
    cudaStreamWaitEvent(0, evWch, 0);
    gemm_mma<0, true,  true,  __half><<<g1h, blk, GSMEM_TOTAL>>>(
        H1h, Wch, conv_b, HCh, RR, K4, RR, nullptr, nullptr, nullptr, nullptr, nullptr);
    cudaStreamWaitEvent(0, evWg, 0);
    gemm_mma<3, false, false, float ><<<ggh, blk, GSMEM_TOTAL>>>(
        HCh, Wgh, nullptr, Ga, 2 * RR, RR, RR, HCh, sp, ba, bx, Gb);
    scan_p1<<<(2 * SCH * RR) / 256, 256>>>(Ga, Gb, CA, CB);
    scan_p2<<<(2 * RR) / 256, 256>>>(CA, CB);
    scan_p3<<<(2 * SCH * RR) / 256, 256>>>(Ga, Gb, CB, H1h);
    cudaStreamWaitEvent(0, evW2, 0);
    gemm_mma<0, true,  false, float ><<<g2h, blk, GSMEM_TOTAL>>>(
        H1h, W2h, b2, out, DD, RR, RR, nullptr, nullptr, nullptr, nullptr, nullptr);

    // join chain B into the main stream
    cudaStreamWaitEvent(0, evB, 0);
}